// round 1
// baseline (speedup 1.0000x reference)
#include <cuda_runtime.h>
#include <cstdint>
#include <cstddef>

// HugeNet: 10000 x (Linear(100,100)+ReLU) scan, then Linear(100,10).
// Persistent kernel: 64 CTAs x 4 batch rows, full layer chain per CTA,
// no grid sync. Weights double(triple)-buffered in smem via cp.async.

#define N_LAYERS 10000
#define D        100
#define D_OUT    10
#define BATCH    256
#define ROWS     4                 // batch rows per CTA
#define NCTA     (BATCH / ROWS)    // 64
#define THREADS  256
#define WBUF     3
#define WELEMS   (D * D)           // 10000 floats = 40KB
#define WPAD     12800             // 128 "rows" x 100 so j in [0,128) reads in-bounds
#define HSTRIDE  104               // 16B-aligned row stride

struct __align__(16) Smem {
    float W[WBUF][WPAD];        // 3 x 51.2KB = 153.6KB (only first 40KB of each filled)
    float h[2][ROWS][HSTRIDE];  // double-buffered activations
    float b[WBUF][128];         // bias buffers
};

__device__ __forceinline__ void fma2(unsigned long long& acc,
                                     unsigned long long a,
                                     unsigned long long b) {
    asm("fma.rn.f32x2 %0, %1, %2, %0;" : "+l"(acc) : "l"(a), "l"(b));
}

__device__ __forceinline__ float2 upk(unsigned long long v) {
    float2 r;
    asm("mov.b64 {%0, %1}, %2;" : "=f"(r.x), "=f"(r.y) : "l"(v));
    return r;
}

__device__ __forceinline__ void cp16(float* dst, const float* src) {
    unsigned s = (unsigned)__cvta_generic_to_shared(dst);
    asm volatile("cp.async.cg.shared.global [%0], [%1], 16;" :: "r"(s), "l"(src));
}

__device__ __forceinline__ void prefetch_layer(Smem* sm, int buf,
                                               const float* __restrict__ Wg,
                                               const float* __restrict__ bg,
                                               int l, int tid) {
    const float* ws = Wg + (size_t)l * WELEMS;
    float* wd = sm->W[buf];
    #pragma unroll
    for (int i = 0; i < 10; i++) {
        int idx = tid + i * THREADS;          // float4 index
        if (idx < WELEMS / 4) cp16(wd + idx * 4, ws + idx * 4);
    }
    if (tid < D / 4) cp16(&sm->b[buf][tid * 4], bg + (size_t)l * D + tid * 4);
}

__global__ void __launch_bounds__(THREADS, 1)
hugenet_kernel(const float* __restrict__ x,
               const float* __restrict__ Wg,
               const float* __restrict__ bg,
               const float* __restrict__ Wo,
               const float* __restrict__ bo,
               float* __restrict__ out) {
    extern __shared__ char smem_raw[];
    Smem* sm = reinterpret_cast<Smem*>(smem_raw);

    const int tid  = threadIdx.x;
    const int j    = tid & 127;   // output column (j >= 100 computes garbage, unused)
    const int half = tid >> 7;    // 0 -> rows {0,1}, 1 -> rows {2,3}
    const int r0   = blockIdx.x * ROWS;

    // Prefetch layers 0 and 1
    prefetch_layer(sm, 0, Wg, bg, 0, tid);
    asm volatile("cp.async.commit_group;");
    prefetch_layer(sm, 1, Wg, bg, 1, tid);
    asm volatile("cp.async.commit_group;");

    // Load initial activations (x rows for this CTA) into h[0]
    for (int idx = tid; idx < ROWS * D; idx += THREADS) {
        int r = idx / D, k = idx % D;
        sm->h[0][r][k] = x[(size_t)(r0 + r) * D + k];
    }

    asm volatile("cp.async.wait_group 1;");   // layer 0 weights resident
    __syncthreads();

    int hb = 0;
    #pragma unroll 1
    for (int l = 0; l < N_LAYERS; l++) {
        const int cur = l % 3;

        // Prefetch layer l+2 into the buffer freed at the end of iter l-1
        if (l + 2 < N_LAYERS)
            prefetch_layer(sm, (l + 2) % 3, Wg, bg, l + 2, tid);
        asm volatile("cp.async.commit_group;");

        // Compute: out[row][j] = relu( sum_k h[row][k] * W[j][k] + b[j] )
        const float* wrow = &sm->W[cur][j * D];
        const float* h0   = sm->h[hb][2 * half];
        const float* h1   = sm->h[hb][2 * half + 1];

        unsigned long long a0 = 0ULL, a1 = 0ULL, c0 = 0ULL, c1 = 0ULL;
        #pragma unroll
        for (int k = 0; k < D; k += 4) {
            ulonglong2 w = *reinterpret_cast<const ulonglong2*>(wrow + k);
            ulonglong2 p = *reinterpret_cast<const ulonglong2*>(h0 + k);
            ulonglong2 q = *reinterpret_cast<const ulonglong2*>(h1 + k);
            fma2(a0, p.x, w.x);
            fma2(a1, q.x, w.x);
            fma2(c0, p.y, w.y);
            fma2(c1, q.y, w.y);
        }

        float2 A0 = upk(a0), C0 = upk(c0), A1 = upk(a1), C1 = upk(c1);
        float bias = sm->b[cur][j];
        float v0 = (A0.x + C0.x) + (A0.y + C0.y) + bias;
        float v1 = (A1.x + C1.x) + (A1.y + C1.y) + bias;
        v0 = fmaxf(v0, 0.0f);
        v1 = fmaxf(v1, 0.0f);

        if (j < D) {
            sm->h[hb ^ 1][2 * half][j]     = v0;
            sm->h[hb ^ 1][2 * half + 1][j] = v1;
        }

        asm volatile("cp.async.wait_group 1;");  // layer l+1 weights resident
        __syncthreads();
        hb ^= 1;
    }

    // Final Linear(100, 10): 40 threads, one (row, out-col) each.
    if (tid < ROWS * D_OUT) {
        int r = tid / D_OUT, o = tid % D_OUT;
        const float* hr = sm->h[hb][r];
        float acc = bo[o];
        #pragma unroll
        for (int k = 0; k < D; k++)
            acc += hr[k] * __ldg(&Wo[o * D + k]);
        out[(size_t)(r0 + r) * D_OUT + o] = acc;
    }
}

extern "C" void kernel_launch(void* const* d_in, const int* in_sizes, int n_in,
                              void* d_out, int out_size) {
    // Map inputs by element count (robust to ordering):
    // x: 256*100=25600, W: 1e8, b: 1e6, W_out: 1000, b_out: 10
    const float *x = nullptr, *W = nullptr, *b = nullptr, *Wo = nullptr, *bo = nullptr;
    for (int i = 0; i < n_in; i++) {
        switch (in_sizes[i]) {
            case 25600:     x  = (const float*)d_in[i]; break;
            case 100000000: W  = (const float*)d_in[i]; break;
            case 1000000:   b  = (const float*)d_in[i]; break;
            case 1000:      Wo = (const float*)d_in[i]; break;
            case 10:        bo = (const float*)d_in[i]; break;
            default: break;
        }
    }

    cudaFuncSetAttribute(hugenet_kernel,
                         cudaFuncAttributeMaxDynamicSharedMemorySize,
                         (int)sizeof(Smem));

    hugenet_kernel<<<NCTA, THREADS, sizeof(Smem)>>>(x, W, b, Wo, bo, (float*)d_out);
}

// round 2
// speedup vs baseline: 1.0936x; 1.0936x over previous
#include <cuda_runtime.h>
#include <cstdint>
#include <cstddef>

// HugeNet: 10000 x (Linear(100,100)+ReLU) scan, then Linear(100,10).
//
// Round 2: weights are pre-shuffled (per launch, by prep_kernel) into a
// thread-interleaved gmem layout so the main kernel streams them with
// coalesced LDG.128 directly into REGISTERS. No smem staging of W at all.
// 64 CTAs x 4 batch rows; 256 threads; thread (j = tid>>1, kh = tid&1)
// computes output column j over k-half kh; pair-reduce via shfl_xor(1).

#define N_LAYERS 10000
#define D        100
#define D_OUT    10
#define BATCH    256
#define ROWS     4
#define NCTA     (BATCH / ROWS)   // 64
#define THREADS  256
#define QUADS    13               // 13 float4 per thread per layer (52 k's, zero-padded)
#define HSTR     104              // h row stride (16B aligned, >= 103)

typedef unsigned long long ull;

// Thread-interleaved padded weights: [(N_LAYERS+2)][QUADS][256] float4 (~532MB, zero-padded)
__device__ __align__(16) float4 g_Wp[(size_t)(N_LAYERS + 2) * QUADS * 256];

// ---------------------------------------------------------------------------
// Preprocessing: W[l][j][k] (row-major) -> g_Wp[(l*QUADS+q)*256 + t]
//   t -> (j = t>>1, kh = t&1), quad q covers k = kh*52 + 4q .. +3
//   zero for j>=100, k+3>=100, or pad layers l>=N_LAYERS.
// ---------------------------------------------------------------------------
__global__ void prep_kernel(const float* __restrict__ W) {
    size_t idx = (size_t)blockIdx.x * blockDim.x + threadIdx.x;
    const size_t total = (size_t)(N_LAYERS + 2) * QUADS * 256;
    if (idx >= total) return;
    int    t    = (int)(idx & 255);
    size_t rest = idx >> 8;
    int    q    = (int)(rest % QUADS);
    size_t l    = rest / QUADS;
    int j  = t >> 1;
    int kh = t & 1;
    int k  = kh * 52 + q * 4;
    float4 v = make_float4(0.f, 0.f, 0.f, 0.f);
    if (l < N_LAYERS && j < D && (k + 3) < D)
        v = *reinterpret_cast<const float4*>(W + l * (size_t)(D * D) + (size_t)j * D + k);
    g_Wp[idx] = v;
}

// ---------------------------------------------------------------------------
// Main kernel
// ---------------------------------------------------------------------------
__device__ __forceinline__ void fma2(ull& a, ull x, ull y) {
    asm("fma.rn.f32x2 %0, %1, %2, %0;" : "+l"(a) : "l"(x), "l"(y));
}
__device__ __forceinline__ float2 upk(ull v) {
    float2 r;
    asm("mov.b64 {%0, %1}, %2;" : "=f"(r.x), "=f"(r.y) : "l"(v));
    return r;
}
__device__ __forceinline__ void ldg2(ull& x, ull& y, const ull* p) {
    asm("ld.global.nc.v2.u64 {%0, %1}, [%2];" : "=l"(x), "=l"(y) : "l"(p));
}

struct W2 { ull x, y; };

__global__ void __launch_bounds__(THREADS, 1)
hugenet_kernel(const float* __restrict__ x,
               const float* __restrict__ bg,
               const float* __restrict__ Wo,
               const float* __restrict__ bo,
               float* __restrict__ out) {
    __shared__ float h[2][ROWS][HSTR];

    const int tid = threadIdx.x;
    const int j   = tid >> 1;
    const int kh  = tid & 1;
    const int kb  = kh * 52;
    const int r0  = blockIdx.x * ROWS;

    // Init h[0] with x; zero the pad columns [100,104) of BOTH buffers
    // (they are read by the kh=1 tail quad; the paired W is zero, but the
    // h value must not be NaN).
    for (int idx = tid; idx < ROWS * D; idx += THREADS) {
        int r = idx / D, k = idx % D;
        h[0][r][k] = x[(size_t)(r0 + r) * D + k];
    }
    if (tid < 32) {
        int buf = tid >> 4, r = (tid >> 2) & 3, c = D + (tid & 3);
        h[buf][r][c] = 0.f;
    }
    __syncthreads();

    const ull* wbase = reinterpret_cast<const ull*>(g_Wp);

    W2 Wa[QUADS], Wb[QUADS];

    auto ldW = [&](W2* Wr, int l) {
        const ull* p = wbase + ((size_t)l * QUADS * 256 + tid) * 2;
        #pragma unroll
        for (int q = 0; q < QUADS; q++)
            ldg2(Wr[q].x, Wr[q].y, p + (size_t)q * 512);
    };

    auto do_layer = [&](const W2* Wr, float bias, int HB) {
        ull a0[ROWS] = {0ull, 0ull, 0ull, 0ull};
        ull a1[ROWS] = {0ull, 0ull, 0ull, 0ull};
        #pragma unroll
        for (int q = 0; q < QUADS; q++) {
            #pragma unroll
            for (int r = 0; r < ROWS; r++) {
                ulonglong2 hv =
                    *reinterpret_cast<const ulonglong2*>(&h[HB][r][kb + q * 4]);
                fma2(a0[r], hv.x, Wr[q].x);
                fma2(a1[r], hv.y, Wr[q].y);
            }
        }
        float v[ROWS];
        #pragma unroll
        for (int r = 0; r < ROWS; r++) {
            float2 u = upk(a0[r]), w = upk(a1[r]);
            float s = (u.x + w.x) + (u.y + w.y);
            s += __shfl_xor_sync(0xffffffffu, s, 1);
            v[r] = fmaxf(s + bias, 0.f);
        }
        if (kh == 0 && j < D) {
            #pragma unroll
            for (int r = 0; r < ROWS; r++) h[HB ^ 1][r][j] = v[r];
        }
        __syncthreads();
    };

    ldW(Wa, 0);
    float bias_a = (j < D) ? __ldg(bg + j) : 0.f;

    #pragma unroll 1
    for (int l = 0; l < N_LAYERS; l += 2) {
        ldW(Wb, l + 1);
        float bias_b = (j < D) ? __ldg(bg + (size_t)(l + 1) * D + j) : 0.f;

        do_layer(Wa, bias_a, 0);   // h[0] -> h[1]

        ldW(Wa, l + 2);            // l+2 == N_LAYERS reads the zeroed pad layer
        bias_a = (j < D && (l + 2) < N_LAYERS)
                     ? __ldg(bg + (size_t)(l + 2) * D + j) : 0.f;

        do_layer(Wb, bias_b, 1);   // h[1] -> h[0]
    }

    // Final Linear(100, 10): 40 threads, one (row, out-col) each. h is in h[0].
    if (tid < ROWS * D_OUT) {
        int r = tid / D_OUT, o = tid % D_OUT;
        const float* hr = h[0][r];
        float acc = bo[o];
        #pragma unroll
        for (int k = 0; k < D; k++)
            acc += hr[k] * __ldg(&Wo[(size_t)o * D + k]);
        out[(size_t)(r0 + r) * D_OUT + o] = acc;
    }
}

// ---------------------------------------------------------------------------
extern "C" void kernel_launch(void* const* d_in, const int* in_sizes, int n_in,
                              void* d_out, int out_size) {
    const float *x = nullptr, *W = nullptr, *b = nullptr, *Wo = nullptr, *bo = nullptr;
    for (int i = 0; i < n_in; i++) {
        switch (in_sizes[i]) {
            case 25600:     x  = (const float*)d_in[i]; break;
            case 100000000: W  = (const float*)d_in[i]; break;
            case 1000000:   b  = (const float*)d_in[i]; break;
            case 1000:      Wo = (const float*)d_in[i]; break;
            case 10:        bo = (const float*)d_in[i]; break;
            default: break;
        }
    }

    const size_t total = (size_t)(N_LAYERS + 2) * QUADS * 256;
    int blocks = (int)((total + 255) / 256);
    prep_kernel<<<blocks, 256>>>(W);

    hugenet_kernel<<<NCTA, THREADS>>>(x, b, Wo, bo, (float*)d_out);
}

// round 3
// speedup vs baseline: 1.1933x; 1.0912x over previous
#include <cuda_runtime.h>
#include <cstdint>
#include <cstddef>

// HugeNet: 10000 x (Linear(100,100)+ReLU) scan, then Linear(100,10).
//
// Round 3: J=2 output columns per thread (halves h-LDS instruction count),
// 4-way k-split with warp-aligned groups and smem partial reduction.
// W pre-shuffled to thread-interleaved fp32 layout, streamed to registers.
// 64 CTAs x 4 batch rows, 256 threads.
//
// Thread (m = tid&63, kq = tid>>6):
//   columns j0 = 2m, j1 = 2m+1 (m < 50 useful)
//   k-range: base KB[kq] = {0,28,52,76}, quads NQ[kq] = {7,6,6,6}

#define N_LAYERS 10000
#define D        100
#define D_OUT    10
#define BATCH    256
#define ROWS     4
#define NCTA     (BATCH / ROWS)   // 64
#define THREADS  256
#define HSTR     104              // h row stride (16B aligned)
#define WSLOTS   14               // float4 slots per thread per layer (max 2*7)

typedef unsigned long long ull;

// [ (N_LAYERS+2) * WSLOTS * 256 ] float4  (~573MB, zero-padded)
__device__ __align__(16) float4 g_Wp[(size_t)(N_LAYERS + 2) * WSLOTS * 256];

__host__ __device__ __forceinline__ int kq_base(int kq) {
    return (kq == 0) ? 0 : (28 + 24 * (kq - 1));   // {0,28,52,76}
}
__host__ __device__ __forceinline__ int kq_nq(int kq) {
    return (kq == 0) ? 7 : 6;                      // quads per group
}

// ---------------------------------------------------------------------------
// prep: W[l][j][k] row-major -> g_Wp[(l*WSLOTS + i)*256 + t]
//   t -> (m = t&63, kq = t>>6);  i = 2*q + jj;  j = 2m+jj;  k = kq_base + 4q
// ---------------------------------------------------------------------------
__global__ void prep_kernel(const float* __restrict__ W) {
    size_t idx = (size_t)blockIdx.x * blockDim.x + threadIdx.x;
    const size_t total = (size_t)(N_LAYERS + 2) * WSLOTS * 256;
    if (idx >= total) return;
    int    t    = (int)(idx & 255);
    size_t rest = idx >> 8;
    int    i    = (int)(rest % WSLOTS);
    size_t l    = rest / WSLOTS;
    int m  = t & 63, kq = t >> 6;
    int jj = i & 1,  q  = i >> 1;
    int j  = 2 * m + jj;
    int k  = kq_base(kq) + 4 * q;
    float4 v = make_float4(0.f, 0.f, 0.f, 0.f);
    if (l < N_LAYERS && j < D && q < kq_nq(kq))
        v = *reinterpret_cast<const float4*>(
                W + l * (size_t)(D * D) + (size_t)j * D + k);
    g_Wp[idx] = v;
}

// ---------------------------------------------------------------------------
__device__ __forceinline__ void fma2(ull& a, ull x, ull y) {
    asm("fma.rn.f32x2 %0, %1, %2, %0;" : "+l"(a) : "l"(x), "l"(y));
}
__device__ __forceinline__ float2 upk(ull v) {
    float2 r;
    asm("mov.b64 {%0, %1}, %2;" : "=f"(r.x), "=f"(r.y) : "l"(v));
    return r;
}

__global__ void __launch_bounds__(THREADS, 1)
hugenet_kernel(const float* __restrict__ x,
               const float* __restrict__ bg,
               const float* __restrict__ Wo,
               const float* __restrict__ bo,
               float* __restrict__ out) {
    __shared__ float h[2][ROWS][HSTR];
    __shared__ float red[3][8][64];   // [kq-1][jj*4+r][m]

    const int tid = threadIdx.x;
    const int m   = tid & 63;
    const int kq  = tid >> 6;
    const int nq  = kq_nq(kq);
    const int kb  = kq_base(kq);
    const int r0  = blockIdx.x * ROWS;

    // init h[0] with x
    for (int idx = tid; idx < ROWS * D; idx += THREADS) {
        int r = idx / D, k = idx % D;
        h[0][r][k] = x[(size_t)(r0 + r) * D + k];
    }
    __syncthreads();

    float4 Wa[WSLOTS], Wb[WSLOTS];

    auto ldW = [&](float4* R, int l) {
        const float4* p = g_Wp + (size_t)l * WSLOTS * 256 + tid;
        #pragma unroll
        for (int i = 0; i < WSLOTS; i++)
            if (i < 2 * nq) R[i] = __ldg(p + (size_t)i * 256);
    };

    float2 bias_a = make_float2(0.f, 0.f), bias_b = make_float2(0.f, 0.f);
    auto ldB = [&](float2& bb, int l) {
        if (tid < 50 && l < N_LAYERS)
            bb = *reinterpret_cast<const float2*>(bg + (size_t)l * D + 2 * tid);
    };

    auto do_layer = [&](const float4* R, float2 bias, int HB) {
        ull a[8];                         // [jj*4 + r], packed even/odd-k
        #pragma unroll
        for (int i = 0; i < 8; i++) a[i] = 0ull;

        #pragma unroll
        for (int q = 0; q < 7; q++) {
            if (q < nq) {
                ulonglong2 w0 = *reinterpret_cast<const ulonglong2*>(&R[2 * q]);
                ulonglong2 w1 = *reinterpret_cast<const ulonglong2*>(&R[2 * q + 1]);
                #pragma unroll
                for (int r = 0; r < ROWS; r++) {
                    ulonglong2 hv =
                        *reinterpret_cast<const ulonglong2*>(&h[HB][r][kb + 4 * q]);
                    fma2(a[r],     hv.x, w0.x);
                    fma2(a[r],     hv.y, w0.y);
                    fma2(a[4 + r], hv.x, w1.x);
                    fma2(a[4 + r], hv.y, w1.y);
                }
            }
        }

        float p[8];
        #pragma unroll
        for (int i = 0; i < 8; i++) {
            float2 u = upk(a[i]);
            p[i] = u.x + u.y;
        }

        if (kq) {
            #pragma unroll
            for (int i = 0; i < 8; i++) red[kq - 1][i][m] = p[i];
        }
        __syncthreads();

        if (tid < 50) {
            float v[8];
            #pragma unroll
            for (int i = 0; i < 8; i++) {
                float s = p[i] + red[0][i][m] + red[1][i][m] + red[2][i][m]
                        + ((i < 4) ? bias.x : bias.y);
                v[i] = fmaxf(s, 0.f);
            }
            #pragma unroll
            for (int r = 0; r < ROWS; r++)
                *reinterpret_cast<float2*>(&h[HB ^ 1][r][2 * m]) =
                    make_float2(v[r], v[4 + r]);
        }
        __syncthreads();
    };

    ldW(Wa, 0);
    ldB(bias_a, 0);

    #pragma unroll 1
    for (int l = 0; l < N_LAYERS; l += 2) {
        ldW(Wb, l + 1);
        ldB(bias_b, l + 1);

        do_layer(Wa, bias_a, 0);          // h[0] -> h[1]

        ldW(Wa, l + 2);                   // pad layers are zeroed
        ldB(bias_a, l + 2);

        do_layer(Wb, bias_b, 1);          // h[1] -> h[0]
    }

    // Final Linear(100, 10): 40 threads, one (row, out-col) each. h in h[0].
    if (tid < ROWS * D_OUT) {
        int r = tid / D_OUT, o = tid % D_OUT;
        const float* hr = h[0][r];
        float acc = bo[o];
        #pragma unroll
        for (int k = 0; k < D; k++)
            acc += hr[k] * __ldg(&Wo[(size_t)o * D + k]);
        out[(size_t)(r0 + r) * D_OUT + o] = acc;
    }
}

// ---------------------------------------------------------------------------
extern "C" void kernel_launch(void* const* d_in, const int* in_sizes, int n_in,
                              void* d_out, int out_size) {
    const float *x = nullptr, *W = nullptr, *b = nullptr, *Wo = nullptr, *bo = nullptr;
    for (int i = 0; i < n_in; i++) {
        switch (in_sizes[i]) {
            case 25600:     x  = (const float*)d_in[i]; break;
            case 100000000: W  = (const float*)d_in[i]; break;
            case 1000000:   b  = (const float*)d_in[i]; break;
            case 1000:      Wo = (const float*)d_in[i]; break;
            case 10:        bo = (const float*)d_in[i]; break;
            default: break;
        }
    }

    const size_t total = (size_t)(N_LAYERS + 2) * WSLOTS * 256;
    int blocks = (int)((total + 255) / 256);
    prep_kernel<<<blocks, 256>>>(W);

    hugenet_kernel<<<NCTA, THREADS>>>(x, b, Wo, bo, (float*)d_out);
}